// round 10
// baseline (speedup 1.0000x reference)
#include <cuda_runtime.h>
#include <cuda_bf16.h>
#include <math.h>
#include <stdint.h>

// Problem dims
#define T_ 1024
#define B_ 256
#define D_ 256
#define H_ 512
#define O_ 256

#define NBLK_A 64

typedef unsigned long long ull;

// bf16 hi/lo planes of hidden history, (t, b, h) layout, h contiguous
__device__ unsigned short g_Hhi[(size_t)T_ * B_ * H_];
__device__ unsigned short g_Hlo[(size_t)T_ * B_ * H_];
__device__ unsigned short g_h0hi[B_ * H_];
__device__ unsigned short g_h0lo[B_ * H_];
__device__ unsigned short g_Vhi[O_ * H_];
__device__ unsigned short g_Vlo[O_ * H_];
__device__ float          g_Ut[D_ * H_];      // U transposed (D, H)

// Per-column-block barriers (8 blocks x 16 CTAs), one cache line each
__device__ unsigned g_cg_cnt[8 * 32];
__device__ unsigned g_cg_gen[8 * 32];

// ---------------- helpers ----------------
__device__ __forceinline__ float bf16hl(unsigned short u) {
    return __uint_as_float((unsigned)u << 16);
}
__device__ __forceinline__ unsigned smem_u32(const void* p) {
    return (unsigned)__cvta_generic_to_shared(p);
}
__device__ __forceinline__ void cp16(unsigned dst, const void* src) {
    asm volatile("cp.async.cg.shared.global [%0], [%1], 16;\n" ::"r"(dst), "l"(src));
}
__device__ __forceinline__ void cp_commit() {
    asm volatile("cp.async.commit_group;\n");
}
template <int N> __device__ __forceinline__ void cp_wait() {
    asm volatile("cp.async.wait_group %0;\n" ::"n"(N));
}
__device__ __forceinline__ float fast_tanh(float x) {
    float e, r;
    asm("ex2.approx.f32 %0, %1;" : "=f"(e) : "f"(x * 2.8853900817779268f));
    asm("rcp.approx.f32 %0, %1;" : "=f"(r) : "f"(e + 1.0f));
    return fmaf(-2.0f, r, 1.0f);
}
__device__ __forceinline__ void ldsm_x4(unsigned* r, unsigned addr) {
    asm volatile("ldmatrix.sync.aligned.m8n8.x4.shared.b16 {%0,%1,%2,%3}, [%4];"
                 : "=r"(r[0]), "=r"(r[1]), "=r"(r[2]), "=r"(r[3]) : "r"(addr));
}
__device__ __forceinline__ void ldsm_x2(unsigned* r, unsigned addr) {
    asm volatile("ldmatrix.sync.aligned.m8n8.x2.shared.b16 {%0,%1}, [%2];"
                 : "=r"(r[0]), "=r"(r[1]) : "r"(addr));
}
__device__ __forceinline__ void mma_bf16(float* d, const unsigned* a, const unsigned* b) {
    asm volatile(
        "mma.sync.aligned.m16n8k16.row.col.f32.bf16.bf16.f32 "
        "{%0,%1,%2,%3}, {%4,%5,%6,%7}, {%8,%9}, {%0,%1,%2,%3};"
        : "+f"(d[0]), "+f"(d[1]), "+f"(d[2]), "+f"(d[3])
        : "r"(a[0]), "r"(a[1]), "r"(a[2]), "r"(a[3]), "r"(b[0]), "r"(b[1]));
}

// Split barrier: arrive returns current generation; wait spins until it advances.
// tid0-only, bracketed by __syncthreads() at call sites. Monotone -> replay-safe.
__device__ __forceinline__ unsigned bar_arrive(int bc) {
    unsigned* cnt = &g_cg_cnt[bc * 32];
    unsigned* gen = &g_cg_gen[bc * 32];
    unsigned my, old;
    asm volatile("ld.relaxed.gpu.u32 %0, [%1];" : "=r"(my) : "l"(gen) : "memory");
    asm volatile("atom.add.release.gpu.u32 %0, [%1], %2;"
                 : "=r"(old) : "l"(cnt), "r"(1u) : "memory");
    if (old == 15u) {
        asm volatile("st.relaxed.gpu.u32 [%0], %1;" :: "l"(cnt), "r"(0u) : "memory");
        asm volatile("st.release.gpu.u32 [%0], %1;" :: "l"(gen), "r"(my + 1u) : "memory");
    }
    return my;
}
__device__ __forceinline__ void bar_wait(int bc, unsigned my) {
    unsigned* gen = &g_cg_gen[bc * 32];
    unsigned g;
    do {
        asm volatile("ld.acquire.gpu.u32 %0, [%1];" : "=r"(g) : "l"(gen) : "memory");
    } while (g == my);
}

// ---------------- prep kernels ----------------
__global__ void prep_Ut(const float* __restrict__ U) {
    int d = blockIdx.x, h = threadIdx.x;
    g_Ut[(size_t)d * H_ + h] = U[(size_t)h * D_ + d];
}
__global__ void prep_h0planes(const float* __restrict__ h0) {
    int b = blockIdx.x, h = threadIdx.x;
    float v = h0[(size_t)h * B_ + b];
    __nv_bfloat16 hi = __float2bfloat16_rn(v);
    __nv_bfloat16 lo = __float2bfloat16_rn(v - __bfloat162float(hi));
    g_h0hi[(size_t)b * H_ + h] = __bfloat16_as_ushort(hi);
    g_h0lo[(size_t)b * H_ + h] = __bfloat16_as_ushort(lo);
}
__global__ void prep_Vplanes(const float* __restrict__ Vm) {
    int o = blockIdx.x, h = threadIdx.x;
    float v = Vm[(size_t)o * H_ + h];
    __nv_bfloat16 hi = __float2bfloat16_rn(v);
    __nv_bfloat16 lo = __float2bfloat16_rn(v - __bfloat162float(hi));
    g_Vhi[(size_t)o * H_ + h] = __bfloat16_as_ushort(hi);
    g_Vlo[(size_t)o * H_ + h] = __bfloat16_as_ushort(lo);
}

// ---------------- Phase A: dual-block pipelined warp-MMA recurrence --------
// smem: Wh 32KB | Wl 32KB | XHH 32KB | XHL 32KB | YHH 32KB | YHL 32KB = 192KB
// RED scratch (33.8KB) aliased onto the idle block's H buffers.
#define WH_OFF 0
#define WL_OFF 32768
#define XHH_OFF 65536
#define XHL_OFF 98304
#define YHH_OFF 131072
#define YHL_OFF 163840
#define SMEM_A_BYTES 196608

__global__ void __launch_bounds__(256, 1)
rnn_recur_mma(const int* __restrict__ inp, const float* __restrict__ W,
              const float* __restrict__ bh)
{
    extern __shared__ char smem[];
    const unsigned sb = smem_u32(smem);

    const int tid = threadIdx.x;
    const int w   = tid >> 5;           // 8 warps, k-split 8 x 64
    const int l   = tid & 31;
    const int bid = blockIdx.x;
    const int r0  = (bid >> 2) * 32;    // 16 row groups
    const int gp  = bid & 3;            // 4 group-pairs
    const int bcX = gp, bcY = gp + 4;
    const int c0X = bcX * 32, c0Y = bcY * 32;

    // one-time: split W slab (32 x 512) into Wh/Wl bf16, swizzled smem
    for (int i = tid; i < 32 * H_; i += 256) {
        int row = i >> 9, k = i & 511;
        float wv = W[(size_t)(r0 + row) * H_ + k];
        __nv_bfloat16 hi = __float2bfloat16_rn(wv);
        __nv_bfloat16 lo = __float2bfloat16_rn(wv - __bfloat162float(hi));
        unsigned off = (unsigned)row * 1024u +
                       ((((unsigned)k >> 3) ^ (unsigned)(row & 7)) << 4) +
                       (unsigned)(k & 7) * 2u;
        *(__nv_bfloat16*)(smem + WH_OFF + off) = hi;
        *(__nv_bfloat16*)(smem + WL_OFF + off) = lo;
    }

    // epilogue ownership: col en (0..31), rows em..em+3
    const int en = tid >> 3;
    const int em = (tid & 7) * 4;
    const float4 bhv = *(const float4*)&bh[r0 + em];
    __syncthreads();

    // ldmatrix lane geometry (warp owns 64-wide k slice)
    const int kw    = w * 64;
    const int quad  = l >> 3, li = l & 7;
    const int a_row = ((quad & 1) << 3) + li;
    const int a_kof = (quad >> 1) << 3;
    const int b_i   = l & 7;
    const int b_half = (l >> 3) & 1;

    unsigned myX = 0, myY = 0;
    float accX[2][4][4], accY[2][4][4];

    // ---- issue cp.async fill of one block's H planes
    auto fill = [&](unsigned hhoff, unsigned hloff, int c0, int t) {
        const unsigned short* sHi =
            (t == 0) ? g_h0hi : g_Hhi + (size_t)(t - 1) * B_ * H_;
        const unsigned short* sLo =
            (t == 0) ? g_h0lo : g_Hlo + (size_t)(t - 1) * B_ * H_;
        #pragma unroll
        for (int j = 0; j < 8; ++j) {
            int i = tid + j * 256;               // 0..2047
            int row = i >> 6, c = i & 63;
            unsigned d = (unsigned)row * 1024u + ((unsigned)(c ^ (row & 7)) << 4);
            size_t src = (size_t)(c0 + row) * H_ + c * 8;
            cp16(sb + hhoff + d, sHi + src);
            cp16(sb + hloff + d, sLo + src);
        }
        cp_commit();
    };

    auto ugather = [&](int c0, int t) -> float4 {
        int x = inp[t * B_ + c0 + en];
        return *(const float4*)&g_Ut[(size_t)x * H_ + r0 + em];
    };

    // ---- compute one block: acc = Wh*hh + Wl*hh + Wh*hl over warp's k slice
    auto compute = [&](unsigned hhoff, unsigned hloff, float (&acc)[2][4][4]) {
        #pragma unroll
        for (int mt = 0; mt < 2; ++mt)
            #pragma unroll
            for (int nt = 0; nt < 4; ++nt)
                #pragma unroll
                for (int q = 0; q < 4; ++q) acc[mt][nt][q] = 0.f;
        #pragma unroll
        for (int ks = 0; ks < 4; ++ks) {
            const int kk = kw + ks * 16;
            unsigned bhh[4][2], bhl[4][2];
            #pragma unroll
            for (int nt = 0; nt < 4; ++nt) {
                int rn = nt * 8 + b_i;
                unsigned base = (unsigned)rn * 1024u +
                    ((((unsigned)(kk + b_half * 8) >> 3) ^ (unsigned)(rn & 7)) << 4);
                ldsm_x2(bhh[nt], sb + hhoff + base);
                ldsm_x2(bhl[nt], sb + hloff + base);
            }
            #pragma unroll
            for (int mt = 0; mt < 2; ++mt) {
                int row = mt * 16 + a_row;
                unsigned aoff = (unsigned)row * 1024u +
                    ((((unsigned)(kk + a_kof) >> 3) ^ (unsigned)(row & 7)) << 4);
                unsigned ah[4], al[4];
                ldsm_x4(ah, sb + WH_OFF + aoff);
                ldsm_x4(al, sb + WL_OFF + aoff);
                #pragma unroll
                for (int nt = 0; nt < 4; ++nt) {
                    mma_bf16(acc[mt][nt], ah, bhh[nt]);
                    mma_bf16(acc[mt][nt], al, bhh[nt]);
                    mma_bf16(acc[mt][nt], ah, bhl[nt]);
                }
            }
        }
    };

    // ---- reduce partials, tanh, store planes, arrive barrier
    auto finish = [&](float (&acc)[2][4][4], unsigned redoff, int c0, int bc,
                      float4 uv, int t, unsigned& my) {
        float* RED = (float*)(smem + redoff);
        {
            int gq = l >> 2, q = l & 3;
            #pragma unroll
            for (int mt = 0; mt < 2; ++mt)
                #pragma unroll
                for (int nt = 0; nt < 4; ++nt) {
                    int m = mt * 16 + gq, n = nt * 8 + 2 * q;
                    RED[(w * 32 + m) * 33 + n]         = acc[mt][nt][0];
                    RED[(w * 32 + m) * 33 + n + 1]     = acc[mt][nt][1];
                    RED[(w * 32 + m + 8) * 33 + n]     = acc[mt][nt][2];
                    RED[(w * 32 + m + 8) * 33 + n + 1] = acc[mt][nt][3];
                }
        }
        __syncthreads();
        unsigned short* pHi = g_Hhi + (size_t)t * B_ * H_;
        unsigned short* pLo = g_Hlo + (size_t)t * B_ * H_;
        unsigned short hu[4], lu[4];
        const float* uvp = &uv.x;
        const float* bhp = &bhv.x;
        #pragma unroll
        for (int r = 0; r < 4; ++r) {
            int m = em + r;
            float s = 0.f;
            #pragma unroll
            for (int ww = 0; ww < 8; ++ww)
                s += RED[(ww * 32 + m) * 33 + en];
            float hv = fast_tanh(s + uvp[r] + bhp[r]);
            __nv_bfloat16 hi = __float2bfloat16_rn(hv);
            __nv_bfloat16 lo = __float2bfloat16_rn(hv - __bfloat162float(hi));
            hu[r] = __bfloat16_as_ushort(hi);
            lu[r] = __bfloat16_as_ushort(lo);
        }
        size_t ofs = (size_t)(c0 + en) * H_ + r0 + em;
        *(uint2*)&pHi[ofs] = *(uint2*)&hu[0];
        *(uint2*)&pLo[ofs] = *(uint2*)&lu[0];
        __syncthreads();
        if (tid == 0) my = bar_arrive(bc);
    };

    // ================= prologue: t = 0 =================
    fill(XHH_OFF, XHL_OFF, c0X, 0);
    float4 uvX = ugather(c0X, 0);
    cp_wait<0>();
    __syncthreads();
    compute(XHH_OFF, XHL_OFF, accX);
    __syncthreads();

    fill(YHH_OFF, YHL_OFF, c0Y, 0);
    float4 uvY = ugather(c0Y, 0);
    finish(accX, XHH_OFF, c0X, bcX, uvX, 0, myX);   // overlaps fillY
    cp_wait<0>();
    __syncthreads();
    compute(YHH_OFF, YHL_OFF, accY);
    __syncthreads();

    // ================= main pipeline =================
    for (int t = 1; t < T_; ++t) {
        // X side
        if (tid == 0) bar_wait(bcX, myX);
        __syncthreads();
        fill(XHH_OFF, XHL_OFF, c0X, t);
        float4 uX = ugather(c0X, t);
        finish(accY, YHH_OFF, c0Y, bcY, uvY, t - 1, myY);   // overlaps fillX
        uvY = uX;  // placeholder swap below (uX is for X; store in temp)
        // NOTE: uvY temporarily holds X's gather; move to uvX now
        { float4 tmp = uvY; uvY = make_float4(0,0,0,0); uvX = tmp; }
        cp_wait<0>();
        __syncthreads();
        compute(XHH_OFF, XHL_OFF, accX);
        __syncthreads();

        // Y side
        if (tid == 0) bar_wait(bcY, myY);
        __syncthreads();
        fill(YHH_OFF, YHL_OFF, c0Y, t);
        uvY = ugather(c0Y, t);
        finish(accX, XHH_OFF, c0X, bcX, uvX, t, myX);       // overlaps fillY
        cp_wait<0>();
        __syncthreads();
        compute(YHH_OFF, YHL_OFF, accY);
        __syncthreads();
    }

    // ================= epilogue: finish Y(1023) =================
    finish(accY, YHH_OFF, c0Y, bcY, uvY, T_ - 1, myY);
}

// ---------------- Phase B: tensor-core logits GEMM (proven round-8) --------
#define PB_AH 0
#define PB_AL 16384
#define PB_VH 32768
#define PB_VL 49152
#define PB_BUF 65536
#define SMEM_B_BYTES (2 * PB_BUF)

__global__ void __launch_bounds__(128, 1)
rnn_logits_mma(const float* __restrict__ by, float* __restrict__ out)
{
    extern __shared__ char smem[];
    const unsigned sb = smem_u32(smem);

    const int t  = blockIdx.z;
    const int ob = blockIdx.x * 64;
    const int bb = blockIdx.y * 64;
    const int tid = threadIdx.x;
    const int w = tid >> 5;
    const int l = tid & 31;
    const int wb = (w >> 1) * 32;
    const int wo = (w & 1) * 32;

    const int quad  = l >> 3, li = l & 7;
    const int a_row = ((quad & 1) << 3) + li;
    const int a_kof = (quad >> 1) << 3;
    const int b_i   = l & 7;
    const int b_half = (l >> 3) & 1;

    const unsigned short* Ahi = g_Hhi + ((size_t)t * B_ + bb) * H_;
    const unsigned short* Alo = g_Hlo + ((size_t)t * B_ + bb) * H_;

    auto fill = [&](int c, unsigned buf) {
        const int kc = c * 128;
        #pragma unroll
        for (int j = 0; j < 8; ++j) {
            int i = tid + j * 128;
            int row = i >> 4, cc = i & 15;
            unsigned dst = (unsigned)(row * 256) + ((unsigned)(cc ^ (row & 7)) << 4);
            size_t srcA = (size_t)row * H_ + kc + cc * 8;
            cp16(sb + buf + PB_AH + dst, Ahi + srcA);
            cp16(sb + buf + PB_AL + dst, Alo + srcA);
            size_t srcV = (size_t)(ob + row) * H_ + kc + cc * 8;
            cp16(sb + buf + PB_VH + dst, g_Vhi + srcV);
            cp16(sb + buf + PB_VL + dst, g_Vlo + srcV);
        }
    };

    float acc[2][4][4];
    #pragma unroll
    for (int mt = 0; mt < 2; ++mt)
        #pragma unroll
        for (int nt = 0; nt < 4; ++nt)
            #pragma unroll
            for (int q = 0; q < 4; ++q) acc[mt][nt][q] = 0.f;

    fill(0, 0);
    cp_commit();

    for (int c = 0; c < 4; ++c) {
        if (c < 3) fill(c + 1, (unsigned)((c + 1) & 1) * PB_BUF);
        cp_commit();
        cp_wait<1>();
        __syncthreads();

        const unsigned buf = sb + (unsigned)(c & 1) * PB_BUF;
        #pragma unroll
        for (int ks = 0; ks < 8; ++ks) {
            const int kk = ks * 16;
            unsigned vh[4][2], vl[4][2];
            #pragma unroll
            for (int nt = 0; nt < 4; ++nt) {
                int rn = wo + nt * 8 + b_i;
                unsigned boff = (unsigned)(rn * 256) +
                    ((((unsigned)(kk + b_half * 8) >> 3) ^ (unsigned)(rn & 7)) << 4);
                ldsm_x2(vh[nt], buf + PB_VH + boff);
                ldsm_x2(vl[nt], buf + PB_VL + boff);
            }
            #pragma unroll
            for (int mt = 0; mt < 2; ++mt) {
                int row = wb + mt * 16 + a_row;
                unsigned aoff = (unsigned)(row * 256) +
                    ((((unsigned)(kk + a_kof) >> 3) ^ (unsigned)(row & 7)) << 4);
                unsigned ah[4], al[4];
                ldsm_x4(ah, buf + PB_AH + aoff);
                ldsm_x4(al, buf + PB_AL + aoff);
                #pragma unroll
                for (int nt = 0; nt < 4; ++nt) {
                    mma_bf16(acc[mt][nt], ah, vh[nt]);
                    mma_bf16(acc[mt][nt], al, vh[nt]);
                    mma_bf16(acc[mt][nt], ah, vl[nt]);
                }
            }
        }
        __syncthreads();
    }

    const int fr = l >> 2, fc = 2 * (l & 3);
    #pragma unroll
    for (int nt = 0; nt < 4; ++nt) {
        int col = ob + wo + nt * 8 + fc;
        float2 b2 = *(const float2*)&by[col];
        #pragma unroll
        for (int mt = 0; mt < 2; ++mt) {
            int r0w = bb + wb + mt * 16 + fr;
            float2 v0 = make_float2(acc[mt][nt][0] + b2.x, acc[mt][nt][1] + b2.y);
            float2 v1 = make_float2(acc[mt][nt][2] + b2.x, acc[mt][nt][3] + b2.y);
            *(float2*)&out[((size_t)t * B_ + r0w) * O_ + col]     = v0;
            *(float2*)&out[((size_t)t * B_ + r0w + 8) * O_ + col] = v1;
        }
    }
}

// Optional hT (H,B) appended after logits: reconstruct from planes
__global__ void copy_hT_kernel(float* __restrict__ out) {
    int h = blockIdx.x;
    int b = threadIdx.x;
    size_t ofs = (size_t)(T_ - 1) * B_ * H_ + (size_t)b * H_ + h;
    out[(size_t)h * B_ + b] = bf16hl(g_Hhi[ofs]) + bf16hl(g_Hlo[ofs]);
}

extern "C" void kernel_launch(void* const* d_in, const int* in_sizes, int n_in,
                              void* d_out, int out_size) {
    const int*   inp = (const int*)d_in[0];
    const float* h0  = (const float*)d_in[1];
    const float* U   = (const float*)d_in[2];
    const float* W   = (const float*)d_in[3];
    const float* Vm  = (const float*)d_in[4];
    const float* bh  = (const float*)d_in[5];
    const float* by  = (const float*)d_in[6];
    float* out = (float*)d_out;

    cudaFuncSetAttribute(rnn_recur_mma,
                         cudaFuncAttributeMaxDynamicSharedMemorySize,
                         (int)SMEM_A_BYTES);
    cudaFuncSetAttribute(rnn_logits_mma,
                         cudaFuncAttributeMaxDynamicSharedMemorySize,
                         (int)SMEM_B_BYTES);

    prep_Ut<<<D_, H_>>>(U);
    prep_h0planes<<<B_, H_>>>(h0);
    prep_Vplanes<<<O_, H_>>>(Vm);

    rnn_recur_mma<<<NBLK_A, 256, SMEM_A_BYTES>>>(inp, W, bh);

    dim3 gridB(O_ / 64, B_ / 64, T_);
    rnn_logits_mma<<<gridB, 128, SMEM_B_BYTES>>>(by, out);

    if (out_size >= T_ * B_ * O_ + H_ * B_) {
        copy_hT_kernel<<<H_, B_>>>(out + (size_t)T_ * B_ * O_);
    }
}

// round 11
// speedup vs baseline: 1.3198x; 1.3198x over previous
#include <cuda_runtime.h>
#include <cuda_bf16.h>
#include <math.h>
#include <stdint.h>

// Problem dims
#define T_ 1024
#define B_ 256
#define D_ 256
#define H_ 512
#define O_ 256

#define NBLK_A 128          // 16 row-groups x 8 column-block pairs

typedef unsigned long long ull;

// bf16 hi/lo planes of hidden history, (t, b, h) layout, h contiguous
__device__ unsigned short g_Hhi[(size_t)T_ * B_ * H_];
__device__ unsigned short g_Hlo[(size_t)T_ * B_ * H_];
__device__ unsigned short g_h0hi[B_ * H_];
__device__ unsigned short g_h0lo[B_ * H_];
__device__ unsigned short g_Vhi[O_ * H_];
__device__ unsigned short g_Vlo[O_ * H_];
__device__ float          g_Ut[D_ * H_];      // U transposed (D, H)

// Per-column-block barriers (16 blocks x 16 CTAs), one cache line each
__device__ unsigned g_cg_cnt[16 * 32];
__device__ unsigned g_cg_gen[16 * 32];

// ---------------- helpers ----------------
__device__ __forceinline__ float bf16hl(unsigned short u) {
    return __uint_as_float((unsigned)u << 16);
}
__device__ __forceinline__ unsigned smem_u32(const void* p) {
    return (unsigned)__cvta_generic_to_shared(p);
}
__device__ __forceinline__ void cp16(unsigned dst, const void* src) {
    asm volatile("cp.async.cg.shared.global [%0], [%1], 16;\n" ::"r"(dst), "l"(src));
}
__device__ __forceinline__ void cp_commit() {
    asm volatile("cp.async.commit_group;\n");
}
template <int N> __device__ __forceinline__ void cp_wait() {
    asm volatile("cp.async.wait_group %0;\n" ::"n"(N));
}
__device__ __forceinline__ float fast_tanh(float x) {
    float e, r;
    asm("ex2.approx.f32 %0, %1;" : "=f"(e) : "f"(x * 2.8853900817779268f));
    asm("rcp.approx.f32 %0, %1;" : "=f"(r) : "f"(e + 1.0f));
    return fmaf(-2.0f, r, 1.0f);
}
__device__ __forceinline__ void ldsm_x4(unsigned* r, unsigned addr) {
    asm volatile("ldmatrix.sync.aligned.m8n8.x4.shared.b16 {%0,%1,%2,%3}, [%4];"
                 : "=r"(r[0]), "=r"(r[1]), "=r"(r[2]), "=r"(r[3]) : "r"(addr));
}
__device__ __forceinline__ void ldsm_x2(unsigned* r, unsigned addr) {
    asm volatile("ldmatrix.sync.aligned.m8n8.x2.shared.b16 {%0,%1}, [%2];"
                 : "=r"(r[0]), "=r"(r[1]) : "r"(addr));
}
__device__ __forceinline__ void mma_bf16(float* d, const unsigned* a, const unsigned* b) {
    asm volatile(
        "mma.sync.aligned.m16n8k16.row.col.f32.bf16.bf16.f32 "
        "{%0,%1,%2,%3}, {%4,%5,%6,%7}, {%8,%9}, {%0,%1,%2,%3};"
        : "+f"(d[0]), "+f"(d[1]), "+f"(d[2]), "+f"(d[3])
        : "r"(a[0]), "r"(a[1]), "r"(a[2]), "r"(a[3]), "r"(b[0]), "r"(b[1]));
}

// Split barrier: arrive returns current generation; wait spins until it advances.
__device__ __forceinline__ unsigned bar_arrive(int bc) {
    unsigned* cnt = &g_cg_cnt[bc * 32];
    unsigned* gen = &g_cg_gen[bc * 32];
    unsigned my, old;
    asm volatile("ld.relaxed.gpu.u32 %0, [%1];" : "=r"(my) : "l"(gen) : "memory");
    asm volatile("atom.add.release.gpu.u32 %0, [%1], %2;"
                 : "=r"(old) : "l"(cnt), "r"(1u) : "memory");
    if (old == 15u) {
        asm volatile("st.relaxed.gpu.u32 [%0], %1;" :: "l"(cnt), "r"(0u) : "memory");
        asm volatile("st.release.gpu.u32 [%0], %1;" :: "l"(gen), "r"(my + 1u) : "memory");
    }
    return my;
}
__device__ __forceinline__ void bar_wait(int bc, unsigned my) {
    unsigned* gen = &g_cg_gen[bc * 32];
    unsigned g;
    do {
        asm volatile("ld.acquire.gpu.u32 %0, [%1];" : "=r"(g) : "l"(gen) : "memory");
    } while (g == my);
}

// ---------------- prep kernels ----------------
__global__ void prep_Ut(const float* __restrict__ U) {
    int d = blockIdx.x, h = threadIdx.x;
    g_Ut[(size_t)d * H_ + h] = U[(size_t)h * D_ + d];
}
__global__ void prep_h0planes(const float* __restrict__ h0) {
    int b = blockIdx.x, h = threadIdx.x;
    float v = h0[(size_t)h * B_ + b];
    __nv_bfloat16 hi = __float2bfloat16_rn(v);
    __nv_bfloat16 lo = __float2bfloat16_rn(v - __bfloat162float(hi));
    g_h0hi[(size_t)b * H_ + h] = __bfloat16_as_ushort(hi);
    g_h0lo[(size_t)b * H_ + h] = __bfloat16_as_ushort(lo);
}
__global__ void prep_Vplanes(const float* __restrict__ Vm) {
    int o = blockIdx.x, h = threadIdx.x;
    float v = Vm[(size_t)o * H_ + h];
    __nv_bfloat16 hi = __float2bfloat16_rn(v);
    __nv_bfloat16 lo = __float2bfloat16_rn(v - __bfloat162float(hi));
    g_Vhi[(size_t)o * H_ + h] = __bfloat16_as_ushort(hi);
    g_Vlo[(size_t)o * H_ + h] = __bfloat16_as_ushort(lo);
}

// ---------------- Phase A: dual 16-col chains, 128 CTAs, 8 warps k-split ----
// smem: Wh 32K | Wl 32K | XHH 16K | XHL 16K | YHH 16K | YHL 16K | RED 17K
#define WH_OFF 0
#define WL_OFF 32768
#define XHH_OFF 65536
#define XHL_OFF 81920
#define YHH_OFF 98304
#define YHL_OFF 114688
#define RED_OFF 131072
#define SMEM_A_BYTES (RED_OFF + 8 * 32 * 17 * 4)

__global__ void __launch_bounds__(256, 1)
rnn_recur_mma(const int* __restrict__ inp, const float* __restrict__ W,
              const float* __restrict__ bh)
{
    extern __shared__ char smem[];
    const unsigned sb = smem_u32(smem);
    float* RED = (float*)(smem + RED_OFF);

    const int tid = threadIdx.x;
    const int w   = tid >> 5;           // 8 warps, k-split 8 x 64
    const int l   = tid & 31;
    const int bid = blockIdx.x;
    const int r0  = (bid >> 3) * 32;    // 16 row groups
    const int gp  = bid & 7;            // 8 column-block pairs
    const int bcX = gp, bcY = gp + 8;
    const int c0X = bcX * 16, c0Y = bcY * 16;

    // one-time: split W slab (32 x 512) into Wh/Wl bf16, swizzled smem
    for (int i = tid; i < 32 * H_; i += 256) {
        int row = i >> 9, k = i & 511;
        float wv = W[(size_t)(r0 + row) * H_ + k];
        __nv_bfloat16 hi = __float2bfloat16_rn(wv);
        __nv_bfloat16 lo = __float2bfloat16_rn(wv - __bfloat162float(hi));
        unsigned off = (unsigned)row * 1024u +
                       ((((unsigned)k >> 3) ^ (unsigned)(row & 7)) << 4) +
                       (unsigned)(k & 7) * 2u;
        *(__nv_bfloat16*)(smem + WH_OFF + off) = hi;
        *(__nv_bfloat16*)(smem + WL_OFF + off) = lo;
    }

    // epilogue ownership: col en (0..15), rows em, em+1
    const int en = tid >> 4;
    const int em = (tid & 15) * 2;
    const float2 bhv = *(const float2*)&bh[r0 + em];
    __syncthreads();

    // ldmatrix lane geometry (warp owns 64-wide k slice)
    const int kw    = w * 64;
    const int quad  = l >> 3, li = l & 7;
    const int a_row = ((quad & 1) << 3) + li;
    const int a_kof = (quad >> 1) << 3;
    const int b_i   = l & 7;
    const int b_half = (l >> 3) & 1;

    unsigned myX = 0, myY = 0;
    float accX[2][2][4], accY[2][2][4];
    float2 uvX, uvY;

    // ---- issue cp.async fill of one chain's H planes (16 cols x 512 k x 2)
    auto fill = [&](unsigned hhoff, unsigned hloff, int c0, int t) {
        const unsigned short* sHi =
            (t == 0) ? g_h0hi : g_Hhi + (size_t)(t - 1) * B_ * H_;
        const unsigned short* sLo =
            (t == 0) ? g_h0lo : g_Hlo + (size_t)(t - 1) * B_ * H_;
        #pragma unroll
        for (int j = 0; j < 4; ++j) {
            int i = tid + j * 256;               // 0..1023
            int row = i >> 6, c = i & 63;
            unsigned d = (unsigned)row * 1024u + ((unsigned)(c ^ (row & 7)) << 4);
            size_t src = (size_t)(c0 + row) * H_ + c * 8;
            cp16(sb + hhoff + d, sHi + src);
            cp16(sb + hloff + d, sLo + src);
        }
        cp_commit();
    };

    auto ugather = [&](int c0, int t) -> float2 {
        int x = inp[t * B_ + c0 + en];
        return *(const float2*)&g_Ut[(size_t)x * H_ + r0 + em];
    };

    // ---- compute one chain: acc = Wh*hh + Wl*hh + Wh*hl over warp's k slice
    auto compute = [&](unsigned hhoff, unsigned hloff, float (&acc)[2][2][4]) {
        #pragma unroll
        for (int mt = 0; mt < 2; ++mt)
            #pragma unroll
            for (int nt = 0; nt < 2; ++nt)
                #pragma unroll
                for (int q = 0; q < 4; ++q) acc[mt][nt][q] = 0.f;
        #pragma unroll
        for (int ks = 0; ks < 4; ++ks) {
            const int kk = kw + ks * 16;
            unsigned bhh[2][2], bhl[2][2];
            #pragma unroll
            for (int nt = 0; nt < 2; ++nt) {
                int rn = nt * 8 + b_i;
                unsigned base = (unsigned)rn * 1024u +
                    ((((unsigned)(kk + b_half * 8) >> 3) ^ (unsigned)(rn & 7)) << 4);
                ldsm_x2(bhh[nt], sb + hhoff + base);
                ldsm_x2(bhl[nt], sb + hloff + base);
            }
            #pragma unroll
            for (int mt = 0; mt < 2; ++mt) {
                int row = mt * 16 + a_row;
                unsigned aoff = (unsigned)row * 1024u +
                    ((((unsigned)(kk + a_kof) >> 3) ^ (unsigned)(row & 7)) << 4);
                unsigned ah[4], al[4];
                ldsm_x4(ah, sb + WH_OFF + aoff);
                ldsm_x4(al, sb + WL_OFF + aoff);
                #pragma unroll
                for (int nt = 0; nt < 2; ++nt) {
                    mma_bf16(acc[mt][nt], ah, bhh[nt]);
                    mma_bf16(acc[mt][nt], al, bhh[nt]);
                    mma_bf16(acc[mt][nt], ah, bhl[nt]);
                }
            }
        }
    };

    // ---- reduce partials, tanh, store planes, arrive barrier
    auto finish = [&](float (&acc)[2][2][4], int c0, int bc,
                      float2 uv, int t, unsigned& my) {
        {
            int gq = l >> 2, q = l & 3;
            #pragma unroll
            for (int mt = 0; mt < 2; ++mt)
                #pragma unroll
                for (int nt = 0; nt < 2; ++nt) {
                    int m = mt * 16 + gq, n = nt * 8 + 2 * q;
                    RED[(w * 32 + m) * 17 + n]         = acc[mt][nt][0];
                    RED[(w * 32 + m) * 17 + n + 1]     = acc[mt][nt][1];
                    RED[(w * 32 + m + 8) * 17 + n]     = acc[mt][nt][2];
                    RED[(w * 32 + m + 8) * 17 + n + 1] = acc[mt][nt][3];
                }
        }
        __syncthreads();
        unsigned short* pHi = g_Hhi + (size_t)t * B_ * H_;
        unsigned short* pLo = g_Hlo + (size_t)t * B_ * H_;
        unsigned short hu[2], lu[2];
        const float* uvp = &uv.x;
        const float* bhp = &bhv.x;
        #pragma unroll
        for (int r = 0; r < 2; ++r) {
            int m = em + r;
            float s = 0.f;
            #pragma unroll
            for (int ww = 0; ww < 8; ++ww)
                s += RED[(ww * 32 + m) * 17 + en];
            float hv = fast_tanh(s + uvp[r] + bhp[r]);
            __nv_bfloat16 hi = __float2bfloat16_rn(hv);
            __nv_bfloat16 lo = __float2bfloat16_rn(hv - __bfloat162float(hi));
            hu[r] = __bfloat16_as_ushort(hi);
            lu[r] = __bfloat16_as_ushort(lo);
        }
        size_t ofs = (size_t)(c0 + en) * H_ + r0 + em;
        *(unsigned*)&pHi[ofs] = *(unsigned*)&hu[0];
        *(unsigned*)&pLo[ofs] = *(unsigned*)&lu[0];
        __syncthreads();
        if (tid == 0) my = bar_arrive(bc);
    };

    // ================= prologue: t = 0 =================
    fill(XHH_OFF, XHL_OFF, c0X, 0);
    uvX = ugather(c0X, 0);
    cp_wait<0>();
    __syncthreads();
    compute(XHH_OFF, XHL_OFF, accX);

    fill(YHH_OFF, YHL_OFF, c0Y, 0);    // no barrier dep: reads h0 planes
    uvY = ugather(c0Y, 0);
    finish(accX, c0X, bcX, uvX, 0, myX);   // overlaps fillY
    cp_wait<0>();
    __syncthreads();
    compute(YHH_OFF, YHL_OFF, accY);

    // ================= main pipeline =================
    for (int t = 1; t < T_; ++t) {
        // X side: wait X producers, fill X(t), finish Y(t-1) under the fill
        if (tid == 0) bar_wait(bcX, myX);
        __syncthreads();
        fill(XHH_OFF, XHL_OFF, c0X, t);
        float2 uXn = ugather(c0X, t);
        finish(accY, c0Y, bcY, uvY, t - 1, myY);
        uvX = uXn;
        cp_wait<0>();
        __syncthreads();
        compute(XHH_OFF, XHL_OFF, accX);

        // Y side: wait Y producers, fill Y(t), finish X(t) under the fill
        if (tid == 0) bar_wait(bcY, myY);
        __syncthreads();
        fill(YHH_OFF, YHL_OFF, c0Y, t);
        float2 uYn = ugather(c0Y, t);
        finish(accX, c0X, bcX, uvX, t, myX);
        uvY = uYn;
        cp_wait<0>();
        __syncthreads();
        compute(YHH_OFF, YHL_OFF, accY);
    }

    // ================= epilogue =================
    finish(accY, c0Y, bcY, uvY, T_ - 1, myY);
}

// ---------------- Phase B: tensor-core logits GEMM (proven round-8) --------
#define PB_AH 0
#define PB_AL 16384
#define PB_VH 32768
#define PB_VL 49152
#define PB_BUF 65536
#define SMEM_B_BYTES (2 * PB_BUF)

__global__ void __launch_bounds__(128, 1)
rnn_logits_mma(const float* __restrict__ by, float* __restrict__ out)
{
    extern __shared__ char smem[];
    const unsigned sb = smem_u32(smem);

    const int t  = blockIdx.z;
    const int ob = blockIdx.x * 64;
    const int bb = blockIdx.y * 64;
    const int tid = threadIdx.x;
    const int w = tid >> 5;
    const int l = tid & 31;
    const int wb = (w >> 1) * 32;
    const int wo = (w & 1) * 32;

    const int quad  = l >> 3, li = l & 7;
    const int a_row = ((quad & 1) << 3) + li;
    const int a_kof = (quad >> 1) << 3;
    const int b_i   = l & 7;
    const int b_half = (l >> 3) & 1;

    const unsigned short* Ahi = g_Hhi + ((size_t)t * B_ + bb) * H_;
    const unsigned short* Alo = g_Hlo + ((size_t)t * B_ + bb) * H_;

    auto fill = [&](int c, unsigned buf) {
        const int kc = c * 128;
        #pragma unroll
        for (int j = 0; j < 8; ++j) {
            int i = tid + j * 128;
            int row = i >> 4, cc = i & 15;
            unsigned dst = (unsigned)(row * 256) + ((unsigned)(cc ^ (row & 7)) << 4);
            size_t srcA = (size_t)row * H_ + kc + cc * 8;
            cp16(sb + buf + PB_AH + dst, Ahi + srcA);
            cp16(sb + buf + PB_AL + dst, Alo + srcA);
            size_t srcV = (size_t)(ob + row) * H_ + kc + cc * 8;
            cp16(sb + buf + PB_VH + dst, g_Vhi + srcV);
            cp16(sb + buf + PB_VL + dst, g_Vlo + srcV);
        }
    };

    float acc[2][4][4];
    #pragma unroll
    for (int mt = 0; mt < 2; ++mt)
        #pragma unroll
        for (int nt = 0; nt < 4; ++nt)
            #pragma unroll
            for (int q = 0; q < 4; ++q) acc[mt][nt][q] = 0.f;

    fill(0, 0);
    cp_commit();

    for (int c = 0; c < 4; ++c) {
        if (c < 3) fill(c + 1, (unsigned)((c + 1) & 1) * PB_BUF);
        cp_commit();
        cp_wait<1>();
        __syncthreads();

        const unsigned buf = sb + (unsigned)(c & 1) * PB_BUF;
        #pragma unroll
        for (int ks = 0; ks < 8; ++ks) {
            const int kk = ks * 16;
            unsigned vh[4][2], vl[4][2];
            #pragma unroll
            for (int nt = 0; nt < 4; ++nt) {
                int rn = wo + nt * 8 + b_i;
                unsigned boff = (unsigned)(rn * 256) +
                    ((((unsigned)(kk + b_half * 8) >> 3) ^ (unsigned)(rn & 7)) << 4);
                ldsm_x2(vh[nt], buf + PB_VH + boff);
                ldsm_x2(vl[nt], buf + PB_VL + boff);
            }
            #pragma unroll
            for (int mt = 0; mt < 2; ++mt) {
                int row = wb + mt * 16 + a_row;
                unsigned aoff = (unsigned)(row * 256) +
                    ((((unsigned)(kk + a_kof) >> 3) ^ (unsigned)(row & 7)) << 4);
                unsigned ah[4], al[4];
                ldsm_x4(ah, buf + PB_AH + aoff);
                ldsm_x4(al, buf + PB_AL + aoff);
                #pragma unroll
                for (int nt = 0; nt < 4; ++nt) {
                    mma_bf16(acc[mt][nt], ah, vh[nt]);
                    mma_bf16(acc[mt][nt], al, vh[nt]);
                    mma_bf16(acc[mt][nt], ah, vl[nt]);
                }
            }
        }
        __syncthreads();
    }

    const int fr = l >> 2, fc = 2 * (l & 3);
    #pragma unroll
    for (int nt = 0; nt < 4; ++nt) {
        int col = ob + wo + nt * 8 + fc;
        float2 b2 = *(const float2*)&by[col];
        #pragma unroll
        for (int mt = 0; mt < 2; ++mt) {
            int r0w = bb + wb + mt * 16 + fr;
            float2 v0 = make_float2(acc[mt][nt][0] + b2.x, acc[mt][nt][1] + b2.y);
            float2 v1 = make_float2(acc[mt][nt][2] + b2.x, acc[mt][nt][3] + b2.y);
            *(float2*)&out[((size_t)t * B_ + r0w) * O_ + col]     = v0;
            *(float2*)&out[((size_t)t * B_ + r0w + 8) * O_ + col] = v1;
        }
    }
}

// Optional hT (H,B) appended after logits: reconstruct from planes
__global__ void copy_hT_kernel(float* __restrict__ out) {
    int h = blockIdx.x;
    int b = threadIdx.x;
    size_t ofs = (size_t)(T_ - 1) * B_ * H_ + (size_t)b * H_ + h;
    out[(size_t)h * B_ + b] = bf16hl(g_Hhi[ofs]) + bf16hl(g_Hlo[ofs]);
}

extern "C" void kernel_launch(void* const* d_in, const int* in_sizes, int n_in,
                              void* d_out, int out_size) {
    const int*   inp = (const int*)d_in[0];
    const float* h0  = (const float*)d_in[1];
    const float* U   = (const float*)d_in[2];
    const float* W   = (const float*)d_in[3];
    const float* Vm  = (const float*)d_in[4];
    const float* bh  = (const float*)d_in[5];
    const float* by  = (const float*)d_in[6];
    float* out = (float*)d_out;

    cudaFuncSetAttribute(rnn_recur_mma,
                         cudaFuncAttributeMaxDynamicSharedMemorySize,
                         (int)SMEM_A_BYTES);
    cudaFuncSetAttribute(rnn_logits_mma,
                         cudaFuncAttributeMaxDynamicSharedMemorySize,
                         (int)SMEM_B_BYTES);

    prep_Ut<<<D_, H_>>>(U);
    prep_h0planes<<<B_, H_>>>(h0);
    prep_Vplanes<<<O_, H_>>>(Vm);

    rnn_recur_mma<<<NBLK_A, 256, SMEM_A_BYTES>>>(inp, W, bh);

    dim3 gridB(O_ / 64, B_ / 64, T_);
    rnn_logits_mma<<<gridB, 128, SMEM_B_BYTES>>>(by, out);

    if (out_size >= T_ * B_ * O_ + H_ * B_) {
        copy_hT_kernel<<<H_, B_>>>(out + (size_t)T_ * B_ * O_);
    }
}

// round 12
// speedup vs baseline: 1.7069x; 1.2933x over previous
#include <cuda_runtime.h>
#include <cuda_bf16.h>
#include <math.h>
#include <stdint.h>

// Problem dims
#define T_ 1024
#define B_ 256
#define D_ 256
#define H_ 512
#define O_ 256

#define NBLK_A 128
#define MB 32
#define NB 32

typedef unsigned long long ull;

// bf16 hi/lo planes of hidden history, (t, b, h) layout, h contiguous
__device__ unsigned short g_Hhi[(size_t)T_ * B_ * H_];
__device__ unsigned short g_Hlo[(size_t)T_ * B_ * H_];
__device__ unsigned short g_h0hi[B_ * H_];
__device__ unsigned short g_h0lo[B_ * H_];
__device__ unsigned short g_Vhi[O_ * H_];
__device__ unsigned short g_Vlo[O_ * H_];
__device__ float          g_Ut[D_ * H_];      // U transposed (D, H)

// Per-column-group barriers (8 groups x 16 CTAs), one cache line each
__device__ unsigned g_cg_cnt[8 * 32];
__device__ unsigned g_cg_gen[8 * 32];

// ---------------- helpers ----------------
__device__ __forceinline__ float bf16hl(unsigned short u) {
    return __uint_as_float((unsigned)u << 16);
}
__device__ __forceinline__ unsigned smem_u32(const void* p) {
    return (unsigned)__cvta_generic_to_shared(p);
}
__device__ __forceinline__ void cp16(unsigned dst, const void* src) {
    asm volatile("cp.async.cg.shared.global [%0], [%1], 16;\n" ::"r"(dst), "l"(src));
}
__device__ __forceinline__ void cp_commit() {
    asm volatile("cp.async.commit_group;\n");
}
template <int N> __device__ __forceinline__ void cp_wait() {
    asm volatile("cp.async.wait_group %0;\n" ::"n"(N));
}
__device__ __forceinline__ float fast_tanh(float x) {
    float e, r;
    asm("ex2.approx.f32 %0, %1;" : "=f"(e) : "f"(x * 2.8853900817779268f));
    asm("rcp.approx.f32 %0, %1;" : "=f"(r) : "f"(e + 1.0f));
    return fmaf(-2.0f, r, 1.0f);
}
__device__ __forceinline__ void ldsm_x4(unsigned* r, unsigned addr) {
    asm volatile("ldmatrix.sync.aligned.m8n8.x4.shared.b16 {%0,%1,%2,%3}, [%4];"
                 : "=r"(r[0]), "=r"(r[1]), "=r"(r[2]), "=r"(r[3]) : "r"(addr));
}
__device__ __forceinline__ void ldsm_x2(unsigned* r, unsigned addr) {
    asm volatile("ldmatrix.sync.aligned.m8n8.x2.shared.b16 {%0,%1}, [%2];"
                 : "=r"(r[0]), "=r"(r[1]) : "r"(addr));
}
__device__ __forceinline__ void mma_bf16(float* d, const unsigned* a, const unsigned* b) {
    asm volatile(
        "mma.sync.aligned.m16n8k16.row.col.f32.bf16.bf16.f32 "
        "{%0,%1,%2,%3}, {%4,%5,%6,%7}, {%8,%9}, {%0,%1,%2,%3};"
        : "+f"(d[0]), "+f"(d[1]), "+f"(d[2]), "+f"(d[3])
        : "r"(a[0]), "r"(a[1]), "r"(a[2]), "r"(a[3]), "r"(b[0]), "r"(b[1]));
}

// Column-group barrier, fence-free (round-9 proven)
__device__ __forceinline__ void group_barrier(int bc) {
    __syncthreads();
    if (threadIdx.x == 0) {
        unsigned* cnt = &g_cg_cnt[bc * 32];
        unsigned* gen = &g_cg_gen[bc * 32];
        unsigned my;
        asm volatile("ld.relaxed.gpu.u32 %0, [%1];" : "=r"(my) : "l"(gen) : "memory");
        unsigned old;
        asm volatile("atom.add.release.gpu.u32 %0, [%1], %2;"
                     : "=r"(old) : "l"(cnt), "r"(1u) : "memory");
        if (old == 15u) {
            asm volatile("st.relaxed.gpu.u32 [%0], %1;" :: "l"(cnt), "r"(0u) : "memory");
            asm volatile("st.release.gpu.u32 [%0], %1;" :: "l"(gen), "r"(my + 1u) : "memory");
        } else {
            unsigned g;
            do {
                asm volatile("ld.acquire.gpu.u32 %0, [%1];" : "=r"(g) : "l"(gen) : "memory");
            } while (g == my);
        }
    }
    __syncthreads();
}

// ---------------- prep kernels ----------------
__global__ void prep_Ut(const float* __restrict__ U) {
    int d = blockIdx.x, h = threadIdx.x;
    g_Ut[(size_t)d * H_ + h] = U[(size_t)h * D_ + d];
}
__global__ void prep_h0planes(const float* __restrict__ h0) {
    int b = blockIdx.x, h = threadIdx.x;
    float v = h0[(size_t)h * B_ + b];
    __nv_bfloat16 hi = __float2bfloat16_rn(v);
    __nv_bfloat16 lo = __float2bfloat16_rn(v - __bfloat162float(hi));
    g_h0hi[(size_t)b * H_ + h] = __bfloat16_as_ushort(hi);
    g_h0lo[(size_t)b * H_ + h] = __bfloat16_as_ushort(lo);
}
__global__ void prep_Vplanes(const float* __restrict__ Vm) {
    int o = blockIdx.x, h = threadIdx.x;
    float v = Vm[(size_t)o * H_ + h];
    __nv_bfloat16 hi = __float2bfloat16_rn(v);
    __nv_bfloat16 lo = __float2bfloat16_rn(v - __bfloat162float(hi));
    g_Vhi[(size_t)o * H_ + h] = __bfloat16_as_ushort(hi);
    g_Vlo[(size_t)o * H_ + h] = __bfloat16_as_ushort(lo);
}

// ---------------- Phase A: warp-MMA recurrence, W frags hoisted ----------
#define WH_OFF 0
#define WL_OFF 32768
#define HH_OFF 65536
#define HL_OFF 98304
#define RED_OFF 131072
#define SMEM_A_BYTES (RED_OFF + 8 * 32 * 33 * 4)

__global__ void __launch_bounds__(256, 1)
rnn_recur_mma(const int* __restrict__ inp, const float* __restrict__ W,
              const float* __restrict__ bh)
{
    extern __shared__ char smem[];
    const unsigned sb = smem_u32(smem);
    float* RED = (float*)(smem + RED_OFF);

    const int tid = threadIdx.x;
    const int w   = tid >> 5;           // 8 warps, k-split 8 x 64
    const int l   = tid & 31;
    const int bid = blockIdx.x;
    const int r0 = (bid >> 3) * MB;
    const int bc = bid & 7;
    const int c0 = bc * NB;

    // one-time: split W slab (32 x 512) into Wh/Wl bf16, swizzled smem
    for (int i = tid; i < MB * H_; i += 256) {
        int row = i >> 9, k = i & 511;
        float wv = W[(size_t)(r0 + row) * H_ + k];
        __nv_bfloat16 hi = __float2bfloat16_rn(wv);
        __nv_bfloat16 lo = __float2bfloat16_rn(wv - __bfloat162float(hi));
        unsigned off = (unsigned)row * 1024u +
                       ((((unsigned)k >> 3) ^ (unsigned)(row & 7)) << 4) +
                       (unsigned)(k & 7) * 2u;
        *(__nv_bfloat16*)(smem + WH_OFF + off) = hi;
        *(__nv_bfloat16*)(smem + WL_OFF + off) = lo;
    }

    // epilogue ownership: col en (0..31), rows em..em+3
    const int en = tid >> 3;
    const int em = (tid & 7) * 4;
    const float4 bhv = *(const float4*)&bh[r0 + em];
    __syncthreads();

    // ldmatrix lane geometry (warp owns 64-wide k slice)
    const int kw    = w * 64;
    const int quad  = l >> 3, li = l & 7;
    const int a_row = ((quad & 1) << 3) + li;
    const int a_kof = (quad >> 1) << 3;
    const int b_i   = l & 7;
    const int b_half = (l >> 3) & 1;

    // ---- hoist: load ALL W fragments into registers once (loop-invariant)
    unsigned wfh[4][2][4], wfl[4][2][4];
    #pragma unroll
    for (int ks = 0; ks < 4; ++ks) {
        const int kk = kw + ks * 16;
        #pragma unroll
        for (int mt = 0; mt < 2; ++mt) {
            int row = mt * 16 + a_row;
            unsigned aoff = (unsigned)row * 1024u +
                ((((unsigned)(kk + a_kof) >> 3) ^ (unsigned)(row & 7)) << 4);
            ldsm_x4(wfh[ks][mt], sb + WH_OFF + aoff);
            ldsm_x4(wfl[ks][mt], sb + WL_OFF + aoff);
        }
    }

    for (int t = 0; t < T_; ++t) {
        const unsigned short* sHi =
            (t == 0) ? g_h0hi : g_Hhi + (size_t)(t - 1) * B_ * H_;
        const unsigned short* sLo =
            (t == 0) ? g_h0lo : g_Hlo + (size_t)(t - 1) * B_ * H_;
        #pragma unroll
        for (int j = 0; j < 8; ++j) {
            int i = tid + j * 256;               // 0..2047
            int row = i >> 6, c = i & 63;
            cp16(sb + HH_OFF + (unsigned)row * 1024u + ((unsigned)(c ^ (row & 7)) << 4),
                 sHi + (size_t)(c0 + row) * H_ + c * 8);
        }
        cp_commit();
        #pragma unroll
        for (int j = 0; j < 8; ++j) {
            int i = tid + j * 256;
            int row = i >> 6, c = i & 63;
            cp16(sb + HL_OFF + (unsigned)row * 1024u + ((unsigned)(c ^ (row & 7)) << 4),
                 sLo + (size_t)(c0 + row) * H_ + c * 8);
        }
        cp_commit();

        // U gather (overlaps cp.async)
        int x = inp[t * B_ + c0 + en];
        float4 uv = *(const float4*)&g_Ut[(size_t)x * H_ + r0 + em];

        float acc[2][4][4];
        #pragma unroll
        for (int mt = 0; mt < 2; ++mt)
            #pragma unroll
            for (int nt = 0; nt < 4; ++nt)
                #pragma unroll
                for (int q = 0; q < 4; ++q) acc[mt][nt][q] = 0.f;

        cp_wait<1>();
        __syncthreads();

        // phase 1: Wh*hh + Wl*hh (W from registers)
        #pragma unroll
        for (int ks = 0; ks < 4; ++ks) {
            const int kk = kw + ks * 16;
            unsigned bfr[4][2];
            #pragma unroll
            for (int nt = 0; nt < 4; ++nt) {
                int rn = nt * 8 + b_i;
                unsigned ba = sb + HH_OFF + (unsigned)rn * 1024u +
                    ((((unsigned)(kk + b_half * 8) >> 3) ^ (unsigned)(rn & 7)) << 4);
                ldsm_x2(bfr[nt], ba);
            }
            #pragma unroll
            for (int mt = 0; mt < 2; ++mt)
                #pragma unroll
                for (int nt = 0; nt < 4; ++nt) {
                    mma_bf16(acc[mt][nt], wfh[ks][mt], bfr[nt]);
                    mma_bf16(acc[mt][nt], wfl[ks][mt], bfr[nt]);
                }
        }

        cp_wait<0>();
        __syncthreads();

        // phase 2: Wh*hl
        #pragma unroll
        for (int ks = 0; ks < 4; ++ks) {
            const int kk = kw + ks * 16;
            unsigned bfr[4][2];
            #pragma unroll
            for (int nt = 0; nt < 4; ++nt) {
                int rn = nt * 8 + b_i;
                unsigned ba = sb + HL_OFF + (unsigned)rn * 1024u +
                    ((((unsigned)(kk + b_half * 8) >> 3) ^ (unsigned)(rn & 7)) << 4);
                ldsm_x2(bfr[nt], ba);
            }
            #pragma unroll
            for (int mt = 0; mt < 2; ++mt)
                #pragma unroll
                for (int nt = 0; nt < 4; ++nt)
                    mma_bf16(acc[mt][nt], wfh[ks][mt], bfr[nt]);
        }

        // cross-warp k reduction (8 partials)
        {
            int g = l >> 2, q = l & 3;
            #pragma unroll
            for (int mt = 0; mt < 2; ++mt)
                #pragma unroll
                for (int nt = 0; nt < 4; ++nt) {
                    int m = mt * 16 + g, n = nt * 8 + 2 * q;
                    RED[(w * 32 + m) * 33 + n]         = acc[mt][nt][0];
                    RED[(w * 32 + m) * 33 + n + 1]     = acc[mt][nt][1];
                    RED[(w * 32 + m + 8) * 33 + n]     = acc[mt][nt][2];
                    RED[(w * 32 + m + 8) * 33 + n + 1] = acc[mt][nt][3];
                }
        }
        __syncthreads();

        // epilogue: sum 8 partials + U + bias, tanh, store planes
        unsigned short* pHi = g_Hhi + (size_t)t * B_ * H_;
        unsigned short* pLo = g_Hlo + (size_t)t * B_ * H_;
        unsigned short hu[4], lu[4];
        const float* uvp = &uv.x;
        const float* bhp = &bhv.x;
        #pragma unroll
        for (int r = 0; r < 4; ++r) {
            int m = em + r;
            float s = 0.f;
            #pragma unroll
            for (int ww = 0; ww < 8; ++ww)
                s += RED[(ww * 32 + m) * 33 + en];
            float hv = fast_tanh(s + uvp[r] + bhp[r]);
            __nv_bfloat16 hi = __float2bfloat16_rn(hv);
            __nv_bfloat16 lo = __float2bfloat16_rn(hv - __bfloat162float(hi));
            hu[r] = __bfloat16_as_ushort(hi);
            lu[r] = __bfloat16_as_ushort(lo);
        }
        size_t ofs = (size_t)(c0 + en) * H_ + r0 + em;
        *(uint2*)&pHi[ofs] = *(uint2*)&hu[0];
        *(uint2*)&pLo[ofs] = *(uint2*)&lu[0];

        group_barrier(bc);
    }
}

// ---------------- Phase B: tensor-core logits GEMM (proven round-8) --------
#define PB_AH 0
#define PB_AL 16384
#define PB_VH 32768
#define PB_VL 49152
#define PB_BUF 65536
#define SMEM_B_BYTES (2 * PB_BUF)

__global__ void __launch_bounds__(128, 1)
rnn_logits_mma(const float* __restrict__ by, float* __restrict__ out)
{
    extern __shared__ char smem[];
    const unsigned sb = smem_u32(smem);

    const int t  = blockIdx.z;
    const int ob = blockIdx.x * 64;
    const int bb = blockIdx.y * 64;
    const int tid = threadIdx.x;
    const int w = tid >> 5;
    const int l = tid & 31;
    const int wb = (w >> 1) * 32;
    const int wo = (w & 1) * 32;

    const int quad  = l >> 3, li = l & 7;
    const int a_row = ((quad & 1) << 3) + li;
    const int a_kof = (quad >> 1) << 3;
    const int b_i   = l & 7;
    const int b_half = (l >> 3) & 1;

    const unsigned short* Ahi = g_Hhi + ((size_t)t * B_ + bb) * H_;
    const unsigned short* Alo = g_Hlo + ((size_t)t * B_ + bb) * H_;

    auto fill = [&](int c, unsigned buf) {
        const int kc = c * 128;
        #pragma unroll
        for (int j = 0; j < 8; ++j) {
            int i = tid + j * 128;
            int row = i >> 4, cc = i & 15;
            unsigned dst = (unsigned)(row * 256) + ((unsigned)(cc ^ (row & 7)) << 4);
            size_t srcA = (size_t)row * H_ + kc + cc * 8;
            cp16(sb + buf + PB_AH + dst, Ahi + srcA);
            cp16(sb + buf + PB_AL + dst, Alo + srcA);
            size_t srcV = (size_t)(ob + row) * H_ + kc + cc * 8;
            cp16(sb + buf + PB_VH + dst, g_Vhi + srcV);
            cp16(sb + buf + PB_VL + dst, g_Vlo + srcV);
        }
    };

    float acc[2][4][4];
    #pragma unroll
    for (int mt = 0; mt < 2; ++mt)
        #pragma unroll
        for (int nt = 0; nt < 4; ++nt)
            #pragma unroll
            for (int q = 0; q < 4; ++q) acc[mt][nt][q] = 0.f;

    fill(0, 0);
    cp_commit();

    for (int c = 0; c < 4; ++c) {
        if (c < 3) fill(c + 1, (unsigned)((c + 1) & 1) * PB_BUF);
        cp_commit();
        cp_wait<1>();
        __syncthreads();

        const unsigned buf = sb + (unsigned)(c & 1) * PB_BUF;
        #pragma unroll
        for (int ks = 0; ks < 8; ++ks) {
            const int kk = ks * 16;
            unsigned vh[4][2], vl[4][2];
            #pragma unroll
            for (int nt = 0; nt < 4; ++nt) {
                int rn = wo + nt * 8 + b_i;
                unsigned boff = (unsigned)(rn * 256) +
                    ((((unsigned)(kk + b_half * 8) >> 3) ^ (unsigned)(rn & 7)) << 4);
                ldsm_x2(vh[nt], buf + PB_VH + boff);
                ldsm_x2(vl[nt], buf + PB_VL + boff);
            }
            #pragma unroll
            for (int mt = 0; mt < 2; ++mt) {
                int row = wb + mt * 16 + a_row;
                unsigned aoff = (unsigned)(row * 256) +
                    ((((unsigned)(kk + a_kof) >> 3) ^ (unsigned)(row & 7)) << 4);
                unsigned ah[4], al[4];
                ldsm_x4(ah, buf + PB_AH + aoff);
                ldsm_x4(al, buf + PB_AL + aoff);
                #pragma unroll
                for (int nt = 0; nt < 4; ++nt) {
                    mma_bf16(acc[mt][nt], ah, vh[nt]);
                    mma_bf16(acc[mt][nt], al, vh[nt]);
                    mma_bf16(acc[mt][nt], ah, vl[nt]);
                }
            }
        }
        __syncthreads();
    }

    const int fr = l >> 2, fc = 2 * (l & 3);
    #pragma unroll
    for (int nt = 0; nt < 4; ++nt) {
        int col = ob + wo + nt * 8 + fc;
        float2 b2 = *(const float2*)&by[col];
        #pragma unroll
        for (int mt = 0; mt < 2; ++mt) {
            int r0w = bb + wb + mt * 16 + fr;
            float2 v0 = make_float2(acc[mt][nt][0] + b2.x, acc[mt][nt][1] + b2.y);
            float2 v1 = make_float2(acc[mt][nt][2] + b2.x, acc[mt][nt][3] + b2.y);
            *(float2*)&out[((size_t)t * B_ + r0w) * O_ + col]     = v0;
            *(float2*)&out[((size_t)t * B_ + r0w + 8) * O_ + col] = v1;
        }
    }
}

// Optional hT (H,B) appended after logits: reconstruct from planes
__global__ void copy_hT_kernel(float* __restrict__ out) {
    int h = blockIdx.x;
    int b = threadIdx.x;
    size_t ofs = (size_t)(T_ - 1) * B_ * H_ + (size_t)b * H_ + h;
    out[(size_t)h * B_ + b] = bf16hl(g_Hhi[ofs]) + bf16hl(g_Hlo[ofs]);
}

extern "C" void kernel_launch(void* const* d_in, const int* in_sizes, int n_in,
                              void* d_out, int out_size) {
    const int*   inp = (const int*)d_in[0];
    const float* h0  = (const float*)d_in[1];
    const float* U   = (const float*)d_in[2];
    const float* W   = (const float*)d_in[3];
    const float* Vm  = (const float*)d_in[4];
    const float* bh  = (const float*)d_in[5];
    const float* by  = (const float*)d_in[6];
    float* out = (float*)d_out;

    cudaFuncSetAttribute(rnn_recur_mma,
                         cudaFuncAttributeMaxDynamicSharedMemorySize,
                         (int)SMEM_A_BYTES);
    cudaFuncSetAttribute(rnn_logits_mma,
                         cudaFuncAttributeMaxDynamicSharedMemorySize,
                         (int)SMEM_B_BYTES);

    prep_Ut<<<D_, H_>>>(U);
    prep_h0planes<<<B_, H_>>>(h0);
    prep_Vplanes<<<O_, H_>>>(Vm);

    rnn_recur_mma<<<NBLK_A, 256, SMEM_A_BYTES>>>(inp, W, bh);

    dim3 gridB(O_ / 64, B_ / 64, T_);
    rnn_logits_mma<<<gridB, 128, SMEM_B_BYTES>>>(by, out);

    if (out_size >= T_ * B_ * O_ + H_ * B_) {
        copy_hT_kernel<<<H_, B_>>>(out + (size_t)T_ * B_ * O_);
    }
}

// round 13
// speedup vs baseline: 2.1006x; 1.2307x over previous
#include <cuda_runtime.h>
#include <cuda_bf16.h>
#include <math.h>
#include <stdint.h>

// Problem dims
#define T_ 1024
#define B_ 256
#define D_ 256
#define H_ 512
#define O_ 256

#define NBLK_A 128
#define MB 32
#define NB 32

typedef unsigned long long ull;

// bf16 hi/lo planes of hidden history, (t, b, h) layout, h contiguous
__device__ unsigned short g_Hhi[(size_t)T_ * B_ * H_];
__device__ unsigned short g_Hlo[(size_t)T_ * B_ * H_];
__device__ unsigned short g_h0hi[B_ * H_];
__device__ unsigned short g_h0lo[B_ * H_];
__device__ unsigned short g_Vhi[O_ * H_];
__device__ unsigned short g_Vlo[O_ * H_];
__device__ float          g_Ut[D_ * H_];      // U transposed (D, H)

// Per-(rowCTA, colgroup) producer flags, one cache line each. Monotone within
// a launch; reset to 0 at kernel tail -> graph-replay safe.
__device__ unsigned g_flag[16 * 8 * 32];
// Gen-based group barrier for the tail cleanup (monotone across replays)
__device__ unsigned g_cg_cnt[8 * 32];
__device__ unsigned g_cg_gen[8 * 32];

// ---------------- helpers ----------------
__device__ __forceinline__ float bf16hl(unsigned short u) {
    return __uint_as_float((unsigned)u << 16);
}
__device__ __forceinline__ unsigned smem_u32(const void* p) {
    return (unsigned)__cvta_generic_to_shared(p);
}
__device__ __forceinline__ void cp16(unsigned dst, const void* src) {
    asm volatile("cp.async.cg.shared.global [%0], [%1], 16;\n" ::"r"(dst), "l"(src));
}
__device__ __forceinline__ void cp_commit() {
    asm volatile("cp.async.commit_group;\n");
}
template <int N> __device__ __forceinline__ void cp_wait() {
    asm volatile("cp.async.wait_group %0;\n" ::"n"(N));
}
__device__ __forceinline__ float fast_tanh(float x) {
    float e, r;
    asm("ex2.approx.f32 %0, %1;" : "=f"(e) : "f"(x * 2.8853900817779268f));
    asm("rcp.approx.f32 %0, %1;" : "=f"(r) : "f"(e + 1.0f));
    return fmaf(-2.0f, r, 1.0f);
}
__device__ __forceinline__ void ldsm_x4(unsigned* r, unsigned addr) {
    asm volatile("ldmatrix.sync.aligned.m8n8.x4.shared.b16 {%0,%1,%2,%3}, [%4];"
                 : "=r"(r[0]), "=r"(r[1]), "=r"(r[2]), "=r"(r[3]) : "r"(addr));
}
__device__ __forceinline__ void ldsm_x2(unsigned* r, unsigned addr) {
    asm volatile("ldmatrix.sync.aligned.m8n8.x2.shared.b16 {%0,%1}, [%2];"
                 : "=r"(r[0]), "=r"(r[1]) : "r"(addr));
}
__device__ __forceinline__ void mma_bf16(float* d, const unsigned* a, const unsigned* b) {
    asm volatile(
        "mma.sync.aligned.m16n8k16.row.col.f32.bf16.bf16.f32 "
        "{%0,%1,%2,%3}, {%4,%5,%6,%7}, {%8,%9}, {%0,%1,%2,%3};"
        : "+f"(d[0]), "+f"(d[1]), "+f"(d[2]), "+f"(d[3])
        : "r"(a[0]), "r"(a[1]), "r"(a[2]), "r"(a[3]), "r"(b[0]), "r"(b[1]));
}

// Tail-only group barrier (16 arrivals), gen-based, replay-safe.
__device__ __forceinline__ void group_barrier(int bc) {
    __syncthreads();
    if (threadIdx.x == 0) {
        unsigned* cnt = &g_cg_cnt[bc * 32];
        unsigned* gen = &g_cg_gen[bc * 32];
        unsigned my;
        asm volatile("ld.relaxed.gpu.u32 %0, [%1];" : "=r"(my) : "l"(gen) : "memory");
        unsigned old;
        asm volatile("atom.add.release.gpu.u32 %0, [%1], %2;"
                     : "=r"(old) : "l"(cnt), "r"(1u) : "memory");
        if (old == 15u) {
            asm volatile("st.relaxed.gpu.u32 [%0], %1;" :: "l"(cnt), "r"(0u) : "memory");
            asm volatile("st.release.gpu.u32 [%0], %1;" :: "l"(gen), "r"(my + 1u) : "memory");
        } else {
            unsigned g;
            do {
                asm volatile("ld.acquire.gpu.u32 %0, [%1];" : "=r"(g) : "l"(gen) : "memory");
            } while (g == my);
        }
    }
    __syncthreads();
}

// ---------------- prep kernels ----------------
__global__ void prep_Ut(const float* __restrict__ U) {
    int d = blockIdx.x, h = threadIdx.x;
    g_Ut[(size_t)d * H_ + h] = U[(size_t)h * D_ + d];
}
__global__ void prep_h0planes(const float* __restrict__ h0) {
    int b = blockIdx.x, h = threadIdx.x;
    float v = h0[(size_t)h * B_ + b];
    __nv_bfloat16 hi = __float2bfloat16_rn(v);
    __nv_bfloat16 lo = __float2bfloat16_rn(v - __bfloat162float(hi));
    g_h0hi[(size_t)b * H_ + h] = __bfloat16_as_ushort(hi);
    g_h0lo[(size_t)b * H_ + h] = __bfloat16_as_ushort(lo);
}
__global__ void prep_Vplanes(const float* __restrict__ Vm) {
    int o = blockIdx.x, h = threadIdx.x;
    float v = Vm[(size_t)o * H_ + h];
    __nv_bfloat16 hi = __float2bfloat16_rn(v);
    __nv_bfloat16 lo = __float2bfloat16_rn(v - __bfloat162float(hi));
    g_Vhi[(size_t)o * H_ + h] = __bfloat16_as_ushort(hi);
    g_Vlo[(size_t)o * H_ + h] = __bfloat16_as_ushort(lo);
}

// ---------------- Phase A: warp-MMA recurrence, per-warp flags ----------
#define WH_OFF 0
#define WL_OFF 32768
#define HH_OFF 65536
#define HL_OFF 98304
#define RED_OFF 131072
#define SMEM_A_BYTES (RED_OFF + 8 * 32 * 33 * 4)

__global__ void __launch_bounds__(256, 1)
rnn_recur_mma(const int* __restrict__ inp, const float* __restrict__ W,
              const float* __restrict__ bh)
{
    extern __shared__ char smem[];
    const unsigned sb = smem_u32(smem);
    float* RED = (float*)(smem + RED_OFF);

    const int tid = threadIdx.x;
    const int w   = tid >> 5;           // 8 warps, k-split 8 x 64
    const int l   = tid & 31;
    const int bid = blockIdx.x;
    const int rr  = bid >> 3;           // row-CTA index (0..15)
    const int r0  = rr * MB;
    const int bc  = bid & 7;
    const int c0  = bc * NB;

    // one-time: split W slab (32 x 512) into Wh/Wl bf16, swizzled smem
    for (int i = tid; i < MB * H_; i += 256) {
        int row = i >> 9, k = i & 511;
        float wv = W[(size_t)(r0 + row) * H_ + k];
        __nv_bfloat16 hi = __float2bfloat16_rn(wv);
        __nv_bfloat16 lo = __float2bfloat16_rn(wv - __bfloat162float(hi));
        unsigned off = (unsigned)row * 1024u +
                       ((((unsigned)k >> 3) ^ (unsigned)(row & 7)) << 4) +
                       (unsigned)(k & 7) * 2u;
        *(__nv_bfloat16*)(smem + WH_OFF + off) = hi;
        *(__nv_bfloat16*)(smem + WL_OFF + off) = lo;
    }

    // epilogue ownership: col en (0..31), rows em..em+3
    const int en = tid >> 3;
    const int em = (tid & 7) * 4;
    const float4 bhv = *(const float4*)&bh[r0 + em];
    __syncthreads();

    // ldmatrix lane geometry (warp owns 64-wide k slice)
    const int kw    = w * 64;
    const int quad  = l >> 3, li = l & 7;
    const int a_row = ((quad & 1) << 3) + li;
    const int a_kof = (quad >> 1) << 3;
    const int b_i   = l & 7;
    const int b_half = (l >> 3) & 1;

    // hoist: all W fragments into registers (loop-invariant)
    unsigned wfh[4][2][4], wfl[4][2][4];
    #pragma unroll
    for (int ks = 0; ks < 4; ++ks) {
        const int kk = kw + ks * 16;
        #pragma unroll
        for (int mt = 0; mt < 2; ++mt) {
            int row = mt * 16 + a_row;
            unsigned aoff = (unsigned)row * 1024u +
                ((((unsigned)(kk + a_kof) >> 3) ^ (unsigned)(row & 7)) << 4);
            ldsm_x4(wfh[ks][mt], sb + WH_OFF + aoff);
            ldsm_x4(wfl[ks][mt], sb + WL_OFF + aoff);
        }
    }

    // this warp's producers: row-CTAs 2w and 2w+1 of the same column group
    const unsigned* fl0 = &g_flag[((2 * w)     * 8 + bc) * 32];
    const unsigned* fl1 = &g_flag[((2 * w + 1) * 8 + bc) * 32];
    unsigned* myflag = &g_flag[(rr * 8 + bc) * 32];

    for (int t = 0; t < T_; ++t) {
        // ---- per-warp: wait for the 2 producers of this k-slice (t>0)
        if (t > 0) {
            unsigned v;
            do {
                asm volatile("ld.acquire.gpu.u32 %0, [%1];" : "=r"(v) : "l"(fl0) : "memory");
            } while (v < (unsigned)t);
            do {
                asm volatile("ld.acquire.gpu.u32 %0, [%1];" : "=r"(v) : "l"(fl1) : "memory");
            } while (v < (unsigned)t);
        }

        // ---- per-warp fill of own k-slice (32 batch rows x 64 k), hi+lo
        {
            const unsigned short* sHi =
                (t == 0) ? g_h0hi : g_Hhi + (size_t)(t - 1) * B_ * H_;
            const unsigned short* sLo =
                (t == 0) ? g_h0lo : g_Hlo + (size_t)(t - 1) * B_ * H_;
            #pragma unroll
            for (int j = 0; j < 8; ++j) {
                int i = l + j * 32;              // 0..255
                int row = i >> 3;
                int cc = 8 * w + (i & 7);
                unsigned d = (unsigned)row * 1024u +
                             ((unsigned)(cc ^ (row & 7)) << 4);
                size_t src = (size_t)(c0 + row) * H_ + cc * 8;
                cp16(sb + HH_OFF + d, sHi + src);
                cp16(sb + HL_OFF + d, sLo + src);
            }
            cp_commit();
        }

        // U gather (overlaps cp.async)
        int x = inp[t * B_ + c0 + en];
        float4 uv = *(const float4*)&g_Ut[(size_t)x * H_ + r0 + em];

        float acc[2][4][4];
        #pragma unroll
        for (int mt = 0; mt < 2; ++mt)
            #pragma unroll
            for (int nt = 0; nt < 4; ++nt)
                #pragma unroll
                for (int q = 0; q < 4; ++q) acc[mt][nt][q] = 0.f;

        cp_wait<0>();
        __syncwarp();

        // single-pass 3-term compute: Wh*hh + Wl*hh + Wh*hl
        #pragma unroll
        for (int ks = 0; ks < 4; ++ks) {
            const int kk = kw + ks * 16;
            unsigned bhh[4][2], bhl[4][2];
            #pragma unroll
            for (int nt = 0; nt < 4; ++nt) {
                int rn = nt * 8 + b_i;
                unsigned base = (unsigned)rn * 1024u +
                    ((((unsigned)(kk + b_half * 8) >> 3) ^ (unsigned)(rn & 7)) << 4);
                ldsm_x2(bhh[nt], sb + HH_OFF + base);
                ldsm_x2(bhl[nt], sb + HL_OFF + base);
            }
            #pragma unroll
            for (int mt = 0; mt < 2; ++mt)
                #pragma unroll
                for (int nt = 0; nt < 4; ++nt) {
                    mma_bf16(acc[mt][nt], wfh[ks][mt], bhh[nt]);
                    mma_bf16(acc[mt][nt], wfl[ks][mt], bhh[nt]);
                    mma_bf16(acc[mt][nt], wfh[ks][mt], bhl[nt]);
                }
        }

        // cross-warp k reduction (8 partials)
        {
            int g = l >> 2, q = l & 3;
            #pragma unroll
            for (int mt = 0; mt < 2; ++mt)
                #pragma unroll
                for (int nt = 0; nt < 4; ++nt) {
                    int m = mt * 16 + g, n = nt * 8 + 2 * q;
                    RED[(w * 32 + m) * 33 + n]         = acc[mt][nt][0];
                    RED[(w * 32 + m) * 33 + n + 1]     = acc[mt][nt][1];
                    RED[(w * 32 + m + 8) * 33 + n]     = acc[mt][nt][2];
                    RED[(w * 32 + m + 8) * 33 + n + 1] = acc[mt][nt][3];
                }
        }
        __syncthreads();

        // epilogue: sum 8 partials + U + bias, tanh, store planes
        unsigned short* pHi = g_Hhi + (size_t)t * B_ * H_;
        unsigned short* pLo = g_Hlo + (size_t)t * B_ * H_;
        unsigned short hu[4], lu[4];
        const float* uvp = &uv.x;
        const float* bhp = &bhv.x;
        #pragma unroll
        for (int r = 0; r < 4; ++r) {
            int m = em + r;
            float s = 0.f;
            #pragma unroll
            for (int ww = 0; ww < 8; ++ww)
                s += RED[(ww * 32 + m) * 33 + en];
            float hv = fast_tanh(s + uvp[r] + bhp[r]);
            __nv_bfloat16 hi = __float2bfloat16_rn(hv);
            __nv_bfloat16 lo = __float2bfloat16_rn(hv - __bfloat162float(hi));
            hu[r] = __bfloat16_as_ushort(hi);
            lu[r] = __bfloat16_as_ushort(lo);
        }
        size_t ofs = (size_t)(c0 + en) * H_ + r0 + em;
        *(uint2*)&pHi[ofs] = *(uint2*)&hu[0];
        *(uint2*)&pLo[ofs] = *(uint2*)&lu[0];

        __syncthreads();
        // publish h_t: flag -> t+1 (release covers all threads' STGs via sync)
        if (tid == 0) {
            unsigned old;
            asm volatile("atom.add.release.gpu.u32 %0, [%1], %2;"
                         : "=r"(old) : "l"(myflag), "r"(1u) : "memory");
        }
    }

    // tail: ensure all consumers in this column group are done, reset flag
    group_barrier(bc);
    if (tid == 0)
        asm volatile("st.relaxed.gpu.u32 [%0], %1;" :: "l"(myflag), "r"(0u) : "memory");
}

// ---------------- Phase B: tensor-core logits GEMM (proven round-8) --------
#define PB_AH 0
#define PB_AL 16384
#define PB_VH 32768
#define PB_VL 49152
#define PB_BUF 65536
#define SMEM_B_BYTES (2 * PB_BUF)

__global__ void __launch_bounds__(128, 1)
rnn_logits_mma(const float* __restrict__ by, float* __restrict__ out)
{
    extern __shared__ char smem[];
    const unsigned sb = smem_u32(smem);

    const int t  = blockIdx.z;
    const int ob = blockIdx.x * 64;
    const int bb = blockIdx.y * 64;
    const int tid = threadIdx.x;
    const int w = tid >> 5;
    const int l = tid & 31;
    const int wb = (w >> 1) * 32;
    const int wo = (w & 1) * 32;

    const int quad  = l >> 3, li = l & 7;
    const int a_row = ((quad & 1) << 3) + li;
    const int a_kof = (quad >> 1) << 3;
    const int b_i   = l & 7;
    const int b_half = (l >> 3) & 1;

    const unsigned short* Ahi = g_Hhi + ((size_t)t * B_ + bb) * H_;
    const unsigned short* Alo = g_Hlo + ((size_t)t * B_ + bb) * H_;

    auto fill = [&](int c, unsigned buf) {
        const int kc = c * 128;
        #pragma unroll
        for (int j = 0; j < 8; ++j) {
            int i = tid + j * 128;
            int row = i >> 4, cc = i & 15;
            unsigned dst = (unsigned)(row * 256) + ((unsigned)(cc ^ (row & 7)) << 4);
            size_t srcA = (size_t)row * H_ + kc + cc * 8;
            cp16(sb + buf + PB_AH + dst, Ahi + srcA);
            cp16(sb + buf + PB_AL + dst, Alo + srcA);
            size_t srcV = (size_t)(ob + row) * H_ + kc + cc * 8;
            cp16(sb + buf + PB_VH + dst, g_Vhi + srcV);
            cp16(sb + buf + PB_VL + dst, g_Vlo + srcV);
        }
    };

    float acc[2][4][4];
    #pragma unroll
    for (int mt = 0; mt < 2; ++mt)
        #pragma unroll
        for (int nt = 0; nt < 4; ++nt)
            #pragma unroll
            for (int q = 0; q < 4; ++q) acc[mt][nt][q] = 0.f;

    fill(0, 0);
    cp_commit();

    for (int c = 0; c < 4; ++c) {
        if (c < 3) fill(c + 1, (unsigned)((c + 1) & 1) * PB_BUF);
        cp_commit();
        cp_wait<1>();
        __syncthreads();

        const unsigned buf = sb + (unsigned)(c & 1) * PB_BUF;
        #pragma unroll
        for (int ks = 0; ks < 8; ++ks) {
            const int kk = ks * 16;
            unsigned vh[4][2], vl[4][2];
            #pragma unroll
            for (int nt = 0; nt < 4; ++nt) {
                int rn = wo + nt * 8 + b_i;
                unsigned boff = (unsigned)(rn * 256) +
                    ((((unsigned)(kk + b_half * 8) >> 3) ^ (unsigned)(rn & 7)) << 4);
                ldsm_x2(vh[nt], buf + PB_VH + boff);
                ldsm_x2(vl[nt], buf + PB_VL + boff);
            }
            #pragma unroll
            for (int mt = 0; mt < 2; ++mt) {
                int row = wb + mt * 16 + a_row;
                unsigned aoff = (unsigned)(row * 256) +
                    ((((unsigned)(kk + a_kof) >> 3) ^ (unsigned)(row & 7)) << 4);
                unsigned ah[4], al[4];
                ldsm_x4(ah, buf + PB_AH + aoff);
                ldsm_x4(al, buf + PB_AL + aoff);
                #pragma unroll
                for (int nt = 0; nt < 4; ++nt) {
                    mma_bf16(acc[mt][nt], ah, vh[nt]);
                    mma_bf16(acc[mt][nt], al, vh[nt]);
                    mma_bf16(acc[mt][nt], ah, vl[nt]);
                }
            }
        }
        __syncthreads();
    }

    const int fr = l >> 2, fc = 2 * (l & 3);
    #pragma unroll
    for (int nt = 0; nt < 4; ++nt) {
        int col = ob + wo + nt * 8 + fc;
        float2 b2 = *(const float2*)&by[col];
        #pragma unroll
        for (int mt = 0; mt < 2; ++mt) {
            int r0w = bb + wb + mt * 16 + fr;
            float2 v0 = make_float2(acc[mt][nt][0] + b2.x, acc[mt][nt][1] + b2.y);
            float2 v1 = make_float2(acc[mt][nt][2] + b2.x, acc[mt][nt][3] + b2.y);
            *(float2*)&out[((size_t)t * B_ + r0w) * O_ + col]     = v0;
            *(float2*)&out[((size_t)t * B_ + r0w + 8) * O_ + col] = v1;
        }
    }
}

// Optional hT (H,B) appended after logits: reconstruct from planes
__global__ void copy_hT_kernel(float* __restrict__ out) {
    int h = blockIdx.x;
    int b = threadIdx.x;
    size_t ofs = (size_t)(T_ - 1) * B_ * H_ + (size_t)b * H_ + h;
    out[(size_t)h * B_ + b] = bf16hl(g_Hhi[ofs]) + bf16hl(g_Hlo[ofs]);
}

extern "C" void kernel_launch(void* const* d_in, const int* in_sizes, int n_in,
                              void* d_out, int out_size) {
    const int*   inp = (const int*)d_in[0];
    const float* h0  = (const float*)d_in[1];
    const float* U   = (const float*)d_in[2];
    const float* W   = (const float*)d_in[3];
    const float* Vm  = (const float*)d_in[4];
    const float* bh  = (const float*)d_in[5];
    const float* by  = (const float*)d_in[6];
    float* out = (float*)d_out;

    cudaFuncSetAttribute(rnn_recur_mma,
                         cudaFuncAttributeMaxDynamicSharedMemorySize,
                         (int)SMEM_A_BYTES);
    cudaFuncSetAttribute(rnn_logits_mma,
                         cudaFuncAttributeMaxDynamicSharedMemorySize,
                         (int)SMEM_B_BYTES);

    prep_Ut<<<D_, H_>>>(U);
    prep_h0planes<<<B_, H_>>>(h0);
    prep_Vplanes<<<O_, H_>>>(Vm);

    rnn_recur_mma<<<NBLK_A, 256, SMEM_A_BYTES>>>(inp, W, bh);

    dim3 gridB(O_ / 64, B_ / 64, T_);
    rnn_logits_mma<<<gridB, 128, SMEM_B_BYTES>>>(by, out);

    if (out_size >= T_ * B_ * O_ + H_ * B_) {
        copy_hT_kernel<<<H_, B_>>>(out + (size_t)T_ * B_ * O_);
    }
}